// round 15
// baseline (speedup 1.0000x reference)
#include <cuda_runtime.h>
#include <math.h>

// EstimateAdj: out = diag(1/rowsum(A*B + I)) @ (A*B + I), N=8192.
// R15: last unmeasured cell = full occupancy AND deep load batch.
//   TPB=512, V=4 (8 front-batched LDG.128/thread), __launch_bounds__(512,4)
//   -> 32-reg cap, 4 CTAs/SM = 64 warps = 100% occupancy.
//   - single pass (768 MB = provable minimum traffic)
//   - branch-free load loop; algebraic diagonal; single-barrier reduction

#define N 8192
#define N4 (N / 4)            // 2048 float4 per row
#define TPB 512
#define V_PER_T (N4 / TPB)    // 4 float4 per thread
#define NWARPS (TPB / 32)     // 16

__global__ __launch_bounds__(TPB, 4)
void estimate_adj_kernel(const float4* __restrict__ A,
                         const float4* __restrict__ B,
                         float4* __restrict__ out) {
    const int row = blockIdx.x;
    const long base = (long)row * N4;
    const int tid = threadIdx.x;

    float4 p[V_PER_T];
    float sum = 0.0f;

    // Branch-free, front-batched coalesced loads (8 LDG.128 in flight).
    #pragma unroll
    for (int j = 0; j < V_PER_T; j++) {
        const int idx = tid + j * TPB;   // 0..2047
        float4 a = A[base + idx];
        float4 b = B[base + idx];
        float4 m;
        m.x = a.x * b.x;
        m.y = a.y * b.y;
        m.z = a.z * b.z;
        m.w = a.w * b.w;
        p[j] = m;
        sum += (m.x + m.y) + (m.z + m.w);
    }

    // Warp reduction
    #pragma unroll
    for (int off = 16; off > 0; off >>= 1)
        sum += __shfl_xor_sync(0xFFFFFFFFu, sum, off);

    __shared__ float warp_sums[NWARPS];
    const int lane = tid & 31;
    const int wid = tid >> 5;
    if (lane == 0) warp_sums[wid] = sum;
    __syncthreads();

    // Every thread finishes the reduction itself (single barrier).
    // Identity contributes exactly +1 to every rowsum.
    float total = 1.0f;
    #pragma unroll
    for (int w = 0; w < NWARPS; w++) total += warp_sums[w];
    float rinv = 1.0f / total;
    if (isinf(rinv)) rinv = 0.0f;

    // Scale and store from registers; diagonal fixup: out[row][row] += rinv.
    const int diag4 = row >> 2;
    #pragma unroll
    for (int j = 0; j < V_PER_T; j++) {
        const int idx = tid + j * TPB;
        float4 m = p[j];
        m.x *= rinv; m.y *= rinv; m.z *= rinv; m.w *= rinv;
        if (idx == diag4) ((float*)&m)[row & 3] += rinv;
        out[base + idx] = m;
    }
}

extern "C" void kernel_launch(void* const* d_in, const int* in_sizes, int n_in,
                              void* d_out, int out_size) {
    const float4* A = (const float4*)d_in[0];   // estimated_adj
    const float4* B = (const float4*)d_in[1];   // ori
    float4* out = (float4*)d_out;
    estimate_adj_kernel<<<N, TPB>>>(A, B, out);
}

// round 16
// speedup vs baseline: 1.0049x; 1.0049x over previous
#include <cuda_runtime.h>
#include <math.h>

// EstimateAdj: out = diag(1/rowsum(A*B + I)) @ (A*B + I), N=8192.
// FINAL (= R12, best-benched variant: 116.77us / 116.96us reproductions):
//   - single pass: inputs read exactly once, output written exactly once
//     (768 MB total = provable minimum traffic for this op)
//   - 1 row per CTA, 1024 threads x 2 float4 held in registers,
//     32 regs -> 2 CTAs/SM = 64 warps (~100% occupancy)
//   - branch-free load loop; diagonal handled algebraically
//     (rowsum = sum(A⊙B) + 1; output diag += rinv at store)
//   - single-barrier block reduction (every thread folds the 32 partials)
// Measured at ~6.85 TB/s = this chip's mixed read/write HBM ceiling.
// Fully-swept falsified levers: occupancy (48/50/69/88/95%), load policy
// (.cs/.nc.256B), store policy (.wt/.cs), deep-batch@full-occ, 2-row
// fusion, persistent CTAs + cp.async double-buffering.

#define N 8192
#define N4 (N / 4)            // 2048 float4 per row
#define TPB 1024
#define V_PER_T (N4 / TPB)    // 2 float4 per thread
#define NWARPS (TPB / 32)     // 32

__global__ __launch_bounds__(TPB, 2)
void estimate_adj_kernel(const float4* __restrict__ A,
                         const float4* __restrict__ B,
                         float4* __restrict__ out) {
    const int row = blockIdx.x;
    const long base = (long)row * N4;
    const int tid = threadIdx.x;

    float4 p[V_PER_T];
    float sum = 0.0f;

    // Branch-free, front-batched coalesced loads.
    #pragma unroll
    for (int j = 0; j < V_PER_T; j++) {
        const int idx = tid + j * TPB;   // 0..2047
        float4 a = A[base + idx];
        float4 b = B[base + idx];
        float4 m;
        m.x = a.x * b.x;
        m.y = a.y * b.y;
        m.z = a.z * b.z;
        m.w = a.w * b.w;
        p[j] = m;
        sum += (m.x + m.y) + (m.z + m.w);
    }

    // Warp reduction
    #pragma unroll
    for (int off = 16; off > 0; off >>= 1)
        sum += __shfl_xor_sync(0xFFFFFFFFu, sum, off);

    __shared__ float warp_sums[NWARPS];
    const int lane = tid & 31;
    const int wid = tid >> 5;
    if (lane == 0) warp_sums[wid] = sum;
    __syncthreads();

    // Every thread finishes the reduction itself (single barrier).
    // Identity contributes exactly +1 to every rowsum.
    float total = 1.0f;
    #pragma unroll
    for (int w = 0; w < NWARPS; w++) total += warp_sums[w];
    float rinv = 1.0f / total;
    if (isinf(rinv)) rinv = 0.0f;

    // Scale and store from registers; diagonal fixup: out[row][row] += rinv.
    const int diag4 = row >> 2;
    #pragma unroll
    for (int j = 0; j < V_PER_T; j++) {
        const int idx = tid + j * TPB;
        float4 m = p[j];
        m.x *= rinv; m.y *= rinv; m.z *= rinv; m.w *= rinv;
        if (idx == diag4) ((float*)&m)[row & 3] += rinv;
        out[base + idx] = m;
    }
}

extern "C" void kernel_launch(void* const* d_in, const int* in_sizes, int n_in,
                              void* d_out, int out_size) {
    const float4* A = (const float4*)d_in[0];   // estimated_adj
    const float4* B = (const float4*)d_in[1];   // ori
    float4* out = (float4*)d_out;
    estimate_adj_kernel<<<N, TPB>>>(A, B, out);
}